// round 14
// baseline (speedup 1.0000x reference)
#include <cuda_runtime.h>
#include <stdint.h>

#define NTOK 16384
#define DDIM 512
#define HDIM 2048
#define NEXP 8
#define NPAIR (NTOK * 2)
#define ROUTE_BLOCKS (NTOK / 256)

// ---------------- device scratch (allocation-free) ----------------
__device__ int g_count[NEXP];
__device__ int g_base[NEXP];
__device__ int g_done1[NEXP];     // completed GEMM1 tiles per expert (PDL gate)
__device__ int g_routeDone;
__device__ int g_i64;
__device__ int g_list[NEXP * NTOK];            // entries: token*2 + slot
__device__ float g_xc[(size_t)NTOK * DDIM];    // tf32-rounded x
__device__ float g_W1t[(size_t)NEXP * DDIM * HDIM];  // [E][H][D] K-major
__device__ float g_W2t[(size_t)NEXP * DDIM * HDIM];  // [E][D][H] K-major
__device__ float g_h[((size_t)NPAIR + 128) * HDIM];  // compacted hidden

// ---------------- helpers ----------------
__device__ __forceinline__ uint32_t smem_to_u32(const void* p) {
    uint32_t a;
    asm("{ .reg .u64 t; cvta.to.shared.u64 t, %1; cvt.u32.u64 %0, t; }"
        : "=r"(a) : "l"(p));
    return a;
}
__device__ __forceinline__ float totf32(float f) {
    uint32_t u;
    asm("cvt.rna.tf32.f32 %0, %1;" : "=r"(u) : "f"(f));
    return __uint_as_float(u);
}
#define CP_ASYNC16(saddr, gptr) \
    asm volatile("cp.async.cg.shared.global [%0], [%1], 16;" :: "r"(saddr), "l"(gptr))
#define CP_COMMIT() asm volatile("cp.async.commit_group;" ::: "memory")
#define CP_WAIT1() asm volatile("cp.async.wait_group 1;" ::: "memory")

__device__ __forceinline__ void mma_tf32(float* c, const uint32_t* a, const uint32_t* b) {
    asm volatile(
        "mma.sync.aligned.m16n8k8.row.col.f32.tf32.tf32.f32 "
        "{%0,%1,%2,%3}, {%4,%5,%6,%7}, {%8,%9}, {%0,%1,%2,%3};"
        : "+f"(c[0]), "+f"(c[1]), "+f"(c[2]), "+f"(c[3])
        : "r"(a[0]), "r"(a[1]), "r"(a[2]), "r"(a[3]), "r"(b[0]), "r"(b[1]));
}
#define LDSM_X4(r0, r1, r2, r3, addr) \
    asm volatile("ldmatrix.sync.aligned.x4.m8n8.shared.b16 {%0,%1,%2,%3}, [%4];" \
                 : "=r"(r0), "=r"(r1), "=r"(r2), "=r"(r3) : "r"(addr))

// ---------------- routing ----------------
__global__ void prep_kernel(const int* __restrict__ aw) {
    __shared__ int nz;
    if (threadIdx.x == 0) nz = 0;
    __syncthreads();
    if (threadIdx.x < 64)
        if (aw[2 * threadIdx.x + 1] != 0) atomicOr(&nz, 1);
    __syncthreads();
    if (threadIdx.x < NEXP) { g_count[threadIdx.x] = 0; g_done1[threadIdx.x] = 0; }
    if (threadIdx.x == 0) { g_i64 = (nz == 0) ? 1 : 0; g_routeDone = 0; }
}

// route + fused prefix (last-arriving block computes g_base)
__global__ void route_kernel(const int* __restrict__ aw) {
    int t = blockIdx.x * blockDim.x + threadIdx.x;
    if (t < NTOK) {
        int e0, e1;
        if (g_i64) { e0 = aw[4 * t]; e1 = aw[4 * t + 2]; }
        else       { e0 = aw[2 * t]; e1 = aw[2 * t + 1]; }
        int p = atomicAdd(&g_count[e0], 1);
        g_list[e0 * NTOK + p] = 2 * t;
        if (e1 != e0) {
            p = atomicAdd(&g_count[e1], 1);
            g_list[e1 * NTOK + p] = 2 * t + 1;
        }
    }
    __syncthreads();
    if (threadIdx.x == 0) {
        __threadfence();                       // release this block's atomics
        int old = atomicAdd(&g_routeDone, 1);
        if (old == ROUTE_BLOCKS - 1) {         // last block: all counts final
            __threadfence();                   // acquire
            int s = 0;
            for (int e = 0; e < NEXP; e++) { g_base[e] = s; s += g_count[e]; }
        }
    }
}

// ---------------- x rounding + output zeroing (fused, same index space) ----
__global__ void xzero_kernel(const float* __restrict__ x, float* __restrict__ out) {
    size_t i = (size_t)blockIdx.x * blockDim.x + threadIdx.x;
    float4 v = ((const float4*)x)[i];
    v.x = totf32(v.x); v.y = totf32(v.y); v.z = totf32(v.z); v.w = totf32(v.w);
    ((float4*)g_xc)[i] = v;
    ((float4*)out)[i] = make_float4(0.f, 0.f, 0.f, 0.f);
}

// ---------------- both weight transposes in one launch ----------------
// z in [0,NEXP): W1 [D][H] -> g_W1t [H][D];  z in [NEXP,2*NEXP): W2 [H][D] -> g_W2t [D][H]
__global__ void transpose_kernel(const float* __restrict__ W1,
                                 const float* __restrict__ W2) {
    __shared__ float t[32][33];
    const int z = blockIdx.z;
    const int which = (z >= NEXP) ? 1 : 0;
    const int e = which ? (z - NEXP) : z;
    const int R = which ? HDIM : DDIM;     // rows of input
    const int C = which ? DDIM : HDIM;     // cols of input
    const float* I = (which ? W2 : W1) + (size_t)e * DDIM * HDIM;
    float* O = (which ? g_W2t : g_W1t) + (size_t)e * DDIM * HDIM;
    const int c0 = (which ? blockIdx.y : blockIdx.x) * 32;
    const int r0 = (which ? blockIdx.x : blockIdx.y) * 32;
    const int tx = threadIdx.x, ty = threadIdx.y;
#pragma unroll
    for (int j = 0; j < 32; j += 8)
        t[ty + j][tx] = totf32(I[(size_t)(r0 + ty + j) * C + c0 + tx]);
    __syncthreads();
#pragma unroll
    for (int j = 0; j < 32; j += 8)
        O[(size_t)(c0 + ty + j) * R + r0 + tx] = t[tx][ty + j];
}

// ---------------- tf32 mma.sync gather-GEMM ----------------
// CTA tile 128x128, BK=32, 3-stage cp.async ring, ldmatrix fragment loads,
// ONE __syncthreads per K-stage, 2 CTAs/SM, ONE commit_group per iteration
// (tail commits an EMPTY group — wait_group counting invariant).
// MODE 2 is SPLIT-K=2 (z = split*NEXP + e), launched with PDL: it begins
// filling SM slots during GEMM1's last wave, gated per-expert on g_done1[e].
#define ASTRIDE 36
#define ABUF (128 * ASTRIDE)
#define ABUFBYTES (ABUF * 4)            // 18432
#define NSTG 3
#define SMEM_BYTES (2 * NSTG * ABUFBYTES)   // 110592

// MODE 1: h = relu(xc @ W1t^T + b1)  K=512,  N=2048, out rows compact
// MODE 2: out[tok] += 0.5*(h @ W2t^T [+ b2]) per split,  N=512
template <int MODE>
__global__ __launch_bounds__(256, 2) void moe_mma(const float* __restrict__ biasAll,
                                                  float* __restrict__ outp) {
    constexpr int KROW = (MODE == 1) ? DDIM : HDIM;      // row stride in K
    constexpr int KD   = (MODE == 1) ? DDIM : HDIM / 2;  // K covered per CTA
    constexpr int ND   = (MODE == 1) ? HDIM : DDIM;
    constexpr int NS = KD / 32;

    if (MODE == 1) {
        // Let the dependent (GEMM2) grid begin launching as soon as all
        // GEMM1 CTAs are scheduled; correctness is enforced by g_done1.
        if (threadIdx.x == 0) cudaTriggerProgrammaticLaunchCompletion();
    }

    const int e = (MODE == 1) ? blockIdx.z : (blockIdx.z & (NEXP - 1));
    const int koff = (MODE == 1) ? 0 : ((int)(blockIdx.z >> 3)) * KD;
    const int count = g_count[e];
    const int m0 = blockIdx.y * 128;
    if (m0 >= count) return;
    const int n0 = blockIdx.x * 128;
    const int baseE = g_base[e];
    const float* __restrict__ W = (MODE == 1 ? g_W1t : g_W2t) + (size_t)e * DDIM * HDIM;
    const float* __restrict__ bias = biasAll + e * ND;
    const int* __restrict__ list = g_list + e * NTOK;

    if (MODE == 2) {
        // gate: all of expert e's GEMM1 tiles done
        const int need = ((count + 127) >> 7) * 16;
        if (threadIdx.x == 0) {
            while (*(volatile int*)&g_done1[e] < need) __nanosleep(100);
        }
        __syncthreads();
        __threadfence();   // acquire g_h stores
    }

    extern __shared__ float smf[];
    const uint32_t sbase = smem_to_u32(smf);

    const int tid = threadIdx.x;
    const int wid = tid >> 5, lid = tid & 31;
    const int wm = wid >> 2, wn = wid & 3;         // warp grid 2(M) x 4(N)
    const int g = lid >> 2, tg = lid & 3;

    // ---- cp.async mapping: 8 x 16B chunks per thread per stage
    const int rA = tid >> 3;       // base row 0..31
    const int c16 = tid & 7;       // 16B chunk within 128B row
    const float* asrc[4];
    const float* bsrc[4];
    uint32_t aoff[4], boff[4];
#pragma unroll
    for (int j = 0; j < 4; j++) {
        int r = rA + 32 * j;
        int gm = m0 + r;
        if (gm >= count) gm = count - 1;
        const float* Ar;
        if (MODE == 1) Ar = g_xc + (size_t)(list[gm] >> 1) * DDIM;
        else           Ar = g_h + (size_t)(baseE + gm) * HDIM + koff;
        asrc[j] = Ar + c16 * 4;
        aoff[j] = sbase + (uint32_t)(r * ASTRIDE + c16 * 4) * 4;
        bsrc[j] = W + (size_t)(n0 + r) * KROW + koff + c16 * 4;
        boff[j] = sbase + (uint32_t)(NSTG * ABUF + r * ASTRIDE + c16 * 4) * 4;
    }

    // ---- ldmatrix per-thread addresses (byte offsets within a stage buffer)
    uint32_t lma[4];
#pragma unroll
    for (int i = 0; i < 4; i++) {
        int row = wm * 64 + i * 16 + ((lid >> 3) & 1) * 8 + (lid & 7);
        lma[i] = (uint32_t)(row * ASTRIDE + ((lid >> 4) & 1) * 4) * 4;
    }
    uint32_t lmb[2];
#pragma unroll
    for (int p = 0; p < 2; p++) {
        int row = wn * 32 + (p * 2 + ((lid >> 4) & 1)) * 8 + (lid & 7);
        lmb[p] = (uint32_t)(row * ASTRIDE + ((lid >> 3) & 1) * 4) * 4;
    }

    float acc[4][4][4];
#pragma unroll
    for (int i = 0; i < 4; i++)
#pragma unroll
        for (int j = 0; j < 4; j++)
#pragma unroll
            for (int q = 0; q < 4; q++) acc[i][j][q] = 0.f;

    auto load_stage = [&](int s) {
        const uint32_t bufo = (uint32_t)(s % NSTG) * ABUFBYTES;
        const int k0 = s * 32;
#pragma unroll
        for (int j = 0; j < 4; j++) {
            CP_ASYNC16(aoff[j] + bufo, asrc[j] + k0);
            CP_ASYNC16(boff[j] + bufo, bsrc[j] + k0);
        }
        CP_COMMIT();
    };

    load_stage(0);
    load_stage(1);

    for (int s = 0; s < NS; s++) {
        CP_WAIT1();          // pending = {s, s+1}; retires group s -> stage s resident
        __syncthreads();     // all threads past wait; stage s-1 readers done
        if (s + 2 < NS) load_stage(s + 2);  // writes buffer (s-1)%3
        else CP_COMMIT();                    // EMPTY group keeps counting invariant

        const uint32_t sa = sbase + (uint32_t)(s % NSTG) * ABUFBYTES;
        const uint32_t sb = sa + (uint32_t)NSTG * ABUFBYTES;
#pragma unroll
        for (int ks = 0; ks < 4; ks++) {
            const uint32_t kb = (uint32_t)ks * 32;  // 8 floats
            uint32_t a[4][4], b[2][4];
#pragma unroll
            for (int i = 0; i < 4; i++)
                LDSM_X4(a[i][0], a[i][1], a[i][2], a[i][3], sa + lma[i] + kb);
#pragma unroll
            for (int p = 0; p < 2; p++)
                LDSM_X4(b[p][0], b[p][1], b[p][2], b[p][3], sb + lmb[p] + kb);
#pragma unroll
            for (int i = 0; i < 4; i++)
#pragma unroll
                for (int j = 0; j < 4; j++)
                    mma_tf32(acc[i][j], a[i], &b[j >> 1][(j & 1) * 2]);
        }
    }

    // ---- epilogue
    const bool addBias = (MODE == 1) || (koff == 0);
#pragma unroll
    for (int i = 0; i < 4; i++) {
#pragma unroll
        for (int half = 0; half < 2; half++) {
            int gm = m0 + wm * 64 + i * 16 + half * 8 + g;
            if (gm >= count) continue;
            int ent = list[gm];
            if (MODE == 1) {
                float* orow = g_h + (size_t)(baseE + gm) * HDIM + n0;
#pragma unroll
                for (int j = 0; j < 4; j++) {
                    int col = wn * 32 + j * 8 + tg * 2;
                    float2 bv = *(const float2*)(bias + n0 + col);
                    float v0 = totf32(fmaxf(acc[i][j][2 * half + 0] + bv.x, 0.f));
                    float v1 = totf32(fmaxf(acc[i][j][2 * half + 1] + bv.y, 0.f));
                    *(float2*)(orow + col) = make_float2(v0, v1);
                }
            } else {
                float* orow = outp + (size_t)(ent >> 1) * DDIM + n0;
#pragma unroll
                for (int j = 0; j < 4; j++) {
                    int col = wn * 32 + j * 8 + tg * 2;
                    float bx = 0.f, by = 0.f;
                    if (addBias) {
                        float2 bv = *(const float2*)(bias + n0 + col);
                        bx = bv.x; by = bv.y;
                    }
                    atomicAdd(orow + col,     0.5f * (acc[i][j][2 * half + 0] + bx));
                    atomicAdd(orow + col + 1, 0.5f * (acc[i][j][2 * half + 1] + by));
                }
            }
        }
    }

    if (MODE == 1) {
        __syncthreads();                 // all epilogue stores issued
        if (threadIdx.x == 0) {
            __threadfence();             // release g_h stores
            atomicAdd(&g_done1[e], 1);
        }
    }
}

// ---------------- launch ----------------
extern "C" void kernel_launch(void* const* d_in, const int* in_sizes, int n_in,
                              void* d_out, int out_size) {
    const float* x  = (const float*)d_in[0];
    const int*   aw = (const int*)d_in[1];
    const float* W1 = (const float*)d_in[2];
    const float* b1 = (const float*)d_in[3];
    const float* W2 = (const float*)d_in[4];
    const float* b2 = (const float*)d_in[5];
    float* out = (float*)d_out;

    cudaFuncSetAttribute(moe_mma<1>, cudaFuncAttributeMaxDynamicSharedMemorySize, SMEM_BYTES);
    cudaFuncSetAttribute(moe_mma<2>, cudaFuncAttributeMaxDynamicSharedMemorySize, SMEM_BYTES);

    prep_kernel<<<1, 256>>>(aw);
    route_kernel<<<ROUTE_BLOCKS, 256>>>(aw);
    xzero_kernel<<<(NTOK * DDIM / 4) / 256, 256>>>(x, out);
    transpose_kernel<<<dim3(HDIM / 32, DDIM / 32, 2 * NEXP), dim3(32, 8)>>>(W1, W2);
    moe_mma<1><<<dim3(HDIM / 128, NTOK / 128, NEXP), 256, SMEM_BYTES>>>(b1, nullptr);

    // GEMM2 with Programmatic Dependent Launch: starts filling SM slots during
    // GEMM1's final wave; per-expert g_done1 spin gates enforce correctness.
    cudaLaunchConfig_t cfg = {};
    cfg.gridDim = dim3(DDIM / 128, NTOK / 128, 2 * NEXP);
    cfg.blockDim = dim3(256, 1, 1);
    cfg.dynamicSmemBytes = SMEM_BYTES;
    cfg.stream = 0;
    cudaLaunchAttribute attr[1];
    attr[0].id = cudaLaunchAttributeProgrammaticStreamSerialization;
    attr[0].val.programmaticStreamSerializationAllowed = 1;
    cfg.attrs = attr;
    cfg.numAttrs = 1;
    cudaLaunchKernelEx(&cfg, moe_mma<2>, b2, out);
}

// round 15
// speedup vs baseline: 1.1720x; 1.1720x over previous
#include <cuda_runtime.h>
#include <stdint.h>

#define NTOK 16384
#define DDIM 512
#define HDIM 2048
#define NEXP 8
#define NPAIR (NTOK * 2)
#define ROUTE_BLOCKS (NTOK / 256)
#define XZERO_BLOCKS (NTOK * DDIM / 4 / 256)       // 8192
#define TRANS_BLOCKS ((HDIM / 32) * (DDIM / 32) * 2 * NEXP)  // 16384
#define AUX_BLOCKS (ROUTE_BLOCKS + XZERO_BLOCKS + TRANS_BLOCKS)

// ---------------- device scratch (allocation-free) ----------------
__device__ int g_count[NEXP];
__device__ int g_base[NEXP];
__device__ int g_routeDone;
__device__ int g_i64;
__device__ int g_list[NEXP * NTOK];            // entries: token*2 + slot
__device__ float g_xc[(size_t)NTOK * DDIM];    // tf32-rounded x
__device__ float g_W1t[(size_t)NEXP * DDIM * HDIM];  // [E][H][D] K-major
__device__ float g_W2t[(size_t)NEXP * DDIM * HDIM];  // [E][D][H] K-major
__device__ float g_h[((size_t)NPAIR + 128) * HDIM];  // compacted hidden

// ---------------- helpers ----------------
__device__ __forceinline__ uint32_t smem_to_u32(const void* p) {
    uint32_t a;
    asm("{ .reg .u64 t; cvta.to.shared.u64 t, %1; cvt.u32.u64 %0, t; }"
        : "=r"(a) : "l"(p));
    return a;
}
__device__ __forceinline__ float totf32(float f) {
    uint32_t u;
    asm("cvt.rna.tf32.f32 %0, %1;" : "=r"(u) : "f"(f));
    return __uint_as_float(u);
}
#define CP_ASYNC16(saddr, gptr) \
    asm volatile("cp.async.cg.shared.global [%0], [%1], 16;" :: "r"(saddr), "l"(gptr))
#define CP_COMMIT() asm volatile("cp.async.commit_group;" ::: "memory")
#define CP_WAIT1() asm volatile("cp.async.wait_group 1;" ::: "memory")

__device__ __forceinline__ void mma_tf32(float* c, const uint32_t* a, const uint32_t* b) {
    asm volatile(
        "mma.sync.aligned.m16n8k8.row.col.f32.tf32.tf32.f32 "
        "{%0,%1,%2,%3}, {%4,%5,%6,%7}, {%8,%9}, {%0,%1,%2,%3};"
        : "+f"(c[0]), "+f"(c[1]), "+f"(c[2]), "+f"(c[3])
        : "r"(a[0]), "r"(a[1]), "r"(a[2]), "r"(a[3]), "r"(b[0]), "r"(b[1]));
}
#define LDSM_X4(r0, r1, r2, r3, addr) \
    asm volatile("ldmatrix.sync.aligned.x4.m8n8.shared.b16 {%0,%1,%2,%3}, [%4];" \
                 : "=r"(r0), "=r"(r1), "=r"(r2), "=r"(r3) : "r"(addr))

// ---------------- prep ----------------
__global__ void prep_kernel(const int* __restrict__ aw) {
    __shared__ int nz;
    if (threadIdx.x == 0) nz = 0;
    __syncthreads();
    if (threadIdx.x < 64)
        if (aw[2 * threadIdx.x + 1] != 0) atomicOr(&nz, 1);
    __syncthreads();
    if (threadIdx.x < NEXP) g_count[threadIdx.x] = 0;
    if (threadIdx.x == 0) { g_i64 = (nz == 0) ? 1 : 0; g_routeDone = 0; }
}

// ---------------- fused aux: route + xzero + transpose in ONE launch -------
// blocks [0, ROUTE_BLOCKS): token routing (+ last-block prefix of g_base)
// blocks [ROUTE_BLOCKS, +XZERO_BLOCKS): x tf32-round + out zeroing
// blocks [.., +TRANS_BLOCKS): both weight transposes (tf32-rounded)
__global__ void aux_kernel(const int* __restrict__ aw,
                           const float* __restrict__ x,
                           float* __restrict__ out,
                           const float* __restrict__ W1,
                           const float* __restrict__ W2) {
    const int bid = blockIdx.x;
    const int tid = threadIdx.x;

    if (bid < ROUTE_BLOCKS) {
        // ---- routing ----
        int t = bid * 256 + tid;
        int e0, e1;
        if (g_i64) { e0 = aw[4 * t]; e1 = aw[4 * t + 2]; }
        else       { e0 = aw[2 * t]; e1 = aw[2 * t + 1]; }
        int p = atomicAdd(&g_count[e0], 1);
        g_list[e0 * NTOK + p] = 2 * t;
        if (e1 != e0) {
            p = atomicAdd(&g_count[e1], 1);
            g_list[e1 * NTOK + p] = 2 * t + 1;
        }
        __syncthreads();
        if (tid == 0) {
            __threadfence();                   // release this block's atomics
            int old = atomicAdd(&g_routeDone, 1);
            if (old == ROUTE_BLOCKS - 1) {     // last route block: counts final
                __threadfence();               // acquire
                int s = 0;
                for (int e = 0; e < NEXP; e++) { g_base[e] = s; s += g_count[e]; }
            }
        }
        return;
    }

    if (bid < ROUTE_BLOCKS + XZERO_BLOCKS) {
        // ---- x tf32-round + zero out ----
        size_t i = (size_t)(bid - ROUTE_BLOCKS) * 256 + tid;
        float4 v = ((const float4*)x)[i];
        v.x = totf32(v.x); v.y = totf32(v.y); v.z = totf32(v.z); v.w = totf32(v.w);
        ((float4*)g_xc)[i] = v;
        ((float4*)out)[i] = make_float4(0.f, 0.f, 0.f, 0.f);
        return;
    }

    // ---- weight transposes ----
    {
        __shared__ float tt[32][33];
        int idx = bid - ROUTE_BLOCKS - XZERO_BLOCKS;     // [0, 16384)
        const int bx = idx & 63;                         // 64
        const int by = (idx >> 6) & 15;                  // 16
        const int z = idx >> 10;                         // 16
        const int which = (z >= NEXP) ? 1 : 0;
        const int e = which ? (z - NEXP) : z;
        const int R = which ? HDIM : DDIM;
        const int C = which ? DDIM : HDIM;
        const float* I = (which ? W2 : W1) + (size_t)e * DDIM * HDIM;
        float* O = (which ? g_W2t : g_W1t) + (size_t)e * DDIM * HDIM;
        const int c0 = (which ? by : bx) * 32;
        const int r0 = (which ? bx : by) * 32;
        const int tx = tid & 31, ty = tid >> 5;          // 32 x 8
#pragma unroll
        for (int j = 0; j < 32; j += 8)
            tt[ty + j][tx] = totf32(I[(size_t)(r0 + ty + j) * C + c0 + tx]);
        __syncthreads();
#pragma unroll
        for (int j = 0; j < 32; j += 8)
            O[(size_t)(c0 + ty + j) * R + r0 + tx] = tt[tx][ty + j];
    }
}

// ---------------- tf32 mma.sync gather-GEMM ----------------
// CTA tile 128x128, BK=32, 3-stage cp.async ring, ldmatrix fragment loads,
// ONE __syncthreads per K-stage, 2 CTAs/SM, ONE commit_group per iteration
// (tail commits an EMPTY group — wait_group counting invariant).
// MODE 2 is SPLIT-K=2 (z = split*NEXP + e); atomicAdd combine, bias on split 0.
#define ASTRIDE 36
#define ABUF (128 * ASTRIDE)
#define ABUFBYTES (ABUF * 4)            // 18432
#define NSTG 3
#define SMEM_BYTES (2 * NSTG * ABUFBYTES)   // 110592

// MODE 1: h = relu(xc @ W1t^T + b1)  K=512,  N=2048, out rows compact
// MODE 2: out[tok] += 0.5*(h @ W2t^T [+ b2]) per split,  N=512
template <int MODE>
__global__ __launch_bounds__(256, 2) void moe_mma(const float* __restrict__ biasAll,
                                                  float* __restrict__ outp) {
    constexpr int KROW = (MODE == 1) ? DDIM : HDIM;      // row stride in K
    constexpr int KD   = (MODE == 1) ? DDIM : HDIM / 2;  // K covered per CTA
    constexpr int ND   = (MODE == 1) ? HDIM : DDIM;
    constexpr int NS = KD / 32;

    const int e = (MODE == 1) ? blockIdx.z : (blockIdx.z & (NEXP - 1));
    const int koff = (MODE == 1) ? 0 : ((int)(blockIdx.z >> 3)) * KD;
    const int count = g_count[e];
    const int m0 = blockIdx.y * 128;
    if (m0 >= count) return;
    const int n0 = blockIdx.x * 128;
    const int baseE = g_base[e];
    const float* __restrict__ W = (MODE == 1 ? g_W1t : g_W2t) + (size_t)e * DDIM * HDIM;
    const float* __restrict__ bias = biasAll + e * ND;
    const int* __restrict__ list = g_list + e * NTOK;

    extern __shared__ float smf[];
    const uint32_t sbase = smem_to_u32(smf);

    const int tid = threadIdx.x;
    const int wid = tid >> 5, lid = tid & 31;
    const int wm = wid >> 2, wn = wid & 3;         // warp grid 2(M) x 4(N)
    const int g = lid >> 2, tg = lid & 3;

    // ---- cp.async mapping: 8 x 16B chunks per thread per stage
    const int rA = tid >> 3;       // base row 0..31
    const int c16 = tid & 7;       // 16B chunk within 128B row
    const float* asrc[4];
    const float* bsrc[4];
    uint32_t aoff[4], boff[4];
#pragma unroll
    for (int j = 0; j < 4; j++) {
        int r = rA + 32 * j;
        int gm = m0 + r;
        if (gm >= count) gm = count - 1;
        const float* Ar;
        if (MODE == 1) Ar = g_xc + (size_t)(list[gm] >> 1) * DDIM;
        else           Ar = g_h + (size_t)(baseE + gm) * HDIM + koff;
        asrc[j] = Ar + c16 * 4;
        aoff[j] = sbase + (uint32_t)(r * ASTRIDE + c16 * 4) * 4;
        bsrc[j] = W + (size_t)(n0 + r) * KROW + koff + c16 * 4;
        boff[j] = sbase + (uint32_t)(NSTG * ABUF + r * ASTRIDE + c16 * 4) * 4;
    }

    // ---- ldmatrix per-thread addresses (byte offsets within a stage buffer)
    uint32_t lma[4];
#pragma unroll
    for (int i = 0; i < 4; i++) {
        int row = wm * 64 + i * 16 + ((lid >> 3) & 1) * 8 + (lid & 7);
        lma[i] = (uint32_t)(row * ASTRIDE + ((lid >> 4) & 1) * 4) * 4;
    }
    uint32_t lmb[2];
#pragma unroll
    for (int p = 0; p < 2; p++) {
        int row = wn * 32 + (p * 2 + ((lid >> 4) & 1)) * 8 + (lid & 7);
        lmb[p] = (uint32_t)(row * ASTRIDE + ((lid >> 3) & 1) * 4) * 4;
    }

    float acc[4][4][4];
#pragma unroll
    for (int i = 0; i < 4; i++)
#pragma unroll
        for (int j = 0; j < 4; j++)
#pragma unroll
            for (int q = 0; q < 4; q++) acc[i][j][q] = 0.f;

    auto load_stage = [&](int s) {
        const uint32_t bufo = (uint32_t)(s % NSTG) * ABUFBYTES;
        const int k0 = s * 32;
#pragma unroll
        for (int j = 0; j < 4; j++) {
            CP_ASYNC16(aoff[j] + bufo, asrc[j] + k0);
            CP_ASYNC16(boff[j] + bufo, bsrc[j] + k0);
        }
        CP_COMMIT();
    };

    load_stage(0);
    load_stage(1);

    for (int s = 0; s < NS; s++) {
        CP_WAIT1();          // pending = {s, s+1}; retires group s -> stage s resident
        __syncthreads();     // all threads past wait; stage s-1 readers done
        if (s + 2 < NS) load_stage(s + 2);  // writes buffer (s-1)%3
        else CP_COMMIT();                    // EMPTY group keeps counting invariant

        const uint32_t sa = sbase + (uint32_t)(s % NSTG) * ABUFBYTES;
        const uint32_t sb = sa + (uint32_t)NSTG * ABUFBYTES;
#pragma unroll
        for (int ks = 0; ks < 4; ks++) {
            const uint32_t kb = (uint32_t)ks * 32;  // 8 floats
            uint32_t a[4][4], b[2][4];
#pragma unroll
            for (int i = 0; i < 4; i++)
                LDSM_X4(a[i][0], a[i][1], a[i][2], a[i][3], sa + lma[i] + kb);
#pragma unroll
            for (int p = 0; p < 2; p++)
                LDSM_X4(b[p][0], b[p][1], b[p][2], b[p][3], sb + lmb[p] + kb);
#pragma unroll
            for (int i = 0; i < 4; i++)
#pragma unroll
                for (int j = 0; j < 4; j++)
                    mma_tf32(acc[i][j], a[i], &b[j >> 1][(j & 1) * 2]);
        }
    }

    // ---- epilogue
    const bool addBias = (MODE == 1) || (koff == 0);
#pragma unroll
    for (int i = 0; i < 4; i++) {
#pragma unroll
        for (int half = 0; half < 2; half++) {
            int gm = m0 + wm * 64 + i * 16 + half * 8 + g;
            if (gm >= count) continue;
            int ent = list[gm];
            if (MODE == 1) {
                float* orow = g_h + (size_t)(baseE + gm) * HDIM + n0;
#pragma unroll
                for (int j = 0; j < 4; j++) {
                    int col = wn * 32 + j * 8 + tg * 2;
                    float2 bv = *(const float2*)(bias + n0 + col);
                    float v0 = totf32(fmaxf(acc[i][j][2 * half + 0] + bv.x, 0.f));
                    float v1 = totf32(fmaxf(acc[i][j][2 * half + 1] + bv.y, 0.f));
                    *(float2*)(orow + col) = make_float2(v0, v1);
                }
            } else {
                float* orow = outp + (size_t)(ent >> 1) * DDIM + n0;
#pragma unroll
                for (int j = 0; j < 4; j++) {
                    int col = wn * 32 + j * 8 + tg * 2;
                    float bx = 0.f, by = 0.f;
                    if (addBias) {
                        float2 bv = *(const float2*)(bias + n0 + col);
                        bx = bv.x; by = bv.y;
                    }
                    atomicAdd(orow + col,     0.5f * (acc[i][j][2 * half + 0] + bx));
                    atomicAdd(orow + col + 1, 0.5f * (acc[i][j][2 * half + 1] + by));
                }
            }
        }
    }
}

// ---------------- launch ----------------
extern "C" void kernel_launch(void* const* d_in, const int* in_sizes, int n_in,
                              void* d_out, int out_size) {
    const float* x  = (const float*)d_in[0];
    const int*   aw = (const int*)d_in[1];
    const float* W1 = (const float*)d_in[2];
    const float* b1 = (const float*)d_in[3];
    const float* W2 = (const float*)d_in[4];
    const float* b2 = (const float*)d_in[5];
    float* out = (float*)d_out;

    cudaFuncSetAttribute(moe_mma<1>, cudaFuncAttributeMaxDynamicSharedMemorySize, SMEM_BYTES);
    cudaFuncSetAttribute(moe_mma<2>, cudaFuncAttributeMaxDynamicSharedMemorySize, SMEM_BYTES);

    prep_kernel<<<1, 256>>>(aw);
    aux_kernel<<<AUX_BLOCKS, 256>>>(aw, x, out, W1, W2);
    moe_mma<1><<<dim3(HDIM / 128, NTOK / 128, NEXP), 256, SMEM_BYTES>>>(b1, nullptr);
    moe_mma<2><<<dim3(DDIM / 128, NTOK / 128, 2 * NEXP), 256, SMEM_BYTES>>>(b2, out);
}